// round 10
// baseline (speedup 1.0000x reference)
#include <cuda_runtime.h>

// SGD_Hankel TT-chain: N=65536, L=128, D=4, R=8, O=2.  S=2 samples/thread.
// R10: R9's burst-free drip pipeline with the pv-clobber bug fixed:
//   the 16-LDG prefetch of chunk c+2 now issues at t==7 AFTER the final
//   two drip-stores of chunk c+1 (R9 issued it at t==6, overwriting pv
//   before iterations 14,15 were published -> rel_err 0.37).
// Layout: per-warp double-buffered xbuf (2 x 8KB), 2 STS.128 drip per step,
// FMA body / swizzle / occupancy (128 thr, 2 CTA/SM) unchanged from R8.

#define DV 4
#define RV 8
#define LV 128
#define NSTEP 126
#define HALF  63

typedef unsigned long long u64;

__device__ __forceinline__ u64 fpack(float a, float b) {
    u64 r; asm("mov.b64 %0, {%1,%2};" : "=l"(r) : "f"(a), "f"(b)); return r;
}
__device__ __forceinline__ u64 fdup(float a) {
    u64 r; asm("mov.b64 %0, {%1,%1};" : "=l"(r) : "f"(a)); return r;
}
__device__ __forceinline__ void funpack(u64 v, float& a, float& b) {
    asm("mov.b64 {%0,%1}, %2;" : "=f"(a), "=f"(b) : "l"(v));
}
__device__ __forceinline__ u64 f2mul(u64 a, u64 b) {
    u64 d; asm("mul.rn.f32x2 %0, %1, %2;" : "=l"(d) : "l"(a), "l"(b)); return d;
}
__device__ __forceinline__ u64 f2fma(u64 a, u64 b, u64 c) {
    u64 d; asm("fma.rn.f32x2 %0, %1, %2, %3;" : "=l"(d) : "l"(a), "l"(b), "l"(c)); return d;
}

// smem: cores [63][3][8][8] + xbuf 4 warps * 2 bufs * 2048 + first/last
#define SCORE_FLOATS (HALF * 3 * RV * RV)      // 12096
#define XBUF_FLOATS  (4 * 2 * 2048)            // 16384
#define SFL_OFF      (SCORE_FLOATS + XBUF_FLOATS)
#define SMEM_FLOATS  (SFL_OFF + 96)
#define SMEM_BYTES   (SMEM_FLOATS * 4)         // 114304 (2 CTAs = 223KB <= 228KB)

// Issue the 16 coalesced LDG.128 for chunk c into the register buffer.
// (N is an exact multiple of 256 -> no guards.)
__device__ __forceinline__ void ldg_chunk(float4 (&pv)[16], const float* __restrict__ x,
                                          int base_w, int lane, int c)
{
    const int s8 = lane & 7;
    const int g  = lane >> 3;
    #pragma unroll
    for (int it = 0; it < 16; ++it) {
        int r = g + it * 4;                           // local row 0..63
        int n = base_w + ((r & 32) ? (r - 32 + 128) : r);
        pv[it] = *(const float4*)(x + (size_t)n * (LV * DV) + (c * 8 + s8) * 4);
    }
}

// One STS.128 of the drip: publish pv[it] into the given buffer, swizzled
// pos=(r+s8)&63. Buffer layout [s8][pos] float4.
__device__ __forceinline__ void sts_it(const float4 (&pv)[16], float* xwb, int lane, int it)
{
    const int s8 = lane & 7;
    const int g  = lane >> 3;
    int r = g + it * 4;
    int pos = (r + s8) & 63;
    *(float4*)(xwb + (s8 * 64 + pos) * 4) = pv[it];
}

// Full-burst publish (init only).
__device__ __forceinline__ void sts_chunk(const float4 (&pv)[16], float* xwb, int lane)
{
    #pragma unroll
    for (int it = 0; it < 16; ++it) sts_it(pv, xwb, lane, it);
}

extern "C" __global__ void __launch_bounds__(128, 2)
tt_chain_kernel(const float* __restrict__ x,
                const float* __restrict__ core_first,
                const float* __restrict__ cores_mid,
                const float* __restrict__ core_last,
                float* __restrict__ out,
                int n_total)
{
    extern __shared__ float sm[];
    float* score  = sm;                    // [63][3][8][8]
    float* xbuf   = sm + SCORE_FLOATS;
    float* sfirst = sm + SFL_OFF;          // 32 floats [j][k]
    float* slast  = sfirst + 32;           // 64 floats [k][j][l]

    const int tid  = threadIdx.x;
    const int lane = tid & 31;
    const int w    = tid >> 5;
    float* xw = xbuf + w * 4096;           // two 2048-float buffers

    const int n0 = blockIdx.x * 256 + tid;
    const int n1 = n0 + 128;
    const int base_w = blockIdx.x * 256 + w * 32;

    float4 pv[16];
    // Prefetch chunk 0 immediately (overlaps core staging + barriers).
    ldg_chunk(pv, x, base_w, lane, 0);

    if (tid < 32)            sfirst[tid] = core_first[tid];
    else if (tid < 96)       slast[tid - 32] = core_last[tid - 32];

    u64 mpA[4], mpB[4];

    #pragma unroll 1
    for (int phase = 0; phase < 2; ++phase) {
        __syncthreads();    // prior-phase consumers done before core overwrite
        // stage cores for this phase: [s][k][j][l] -> [s][j][k][l], j<3
        for (int u = tid; u < HALF * 48; u += 128) {
            int st = u / 48;
            int rr = u - st * 48;
            int j = rr >> 4, k = (rr >> 1) & 7, h = rr & 1;
            float4 v = *(const float4*)(cores_mid
                        + (((size_t)(phase * HALF + st) * RV + k) * DV + j) * RV + h * 4);
            *(float4*)(score + ((st * 3 + j) * RV + k) * RV + h * 4) = v;
        }
        __syncthreads();

        if (phase == 0) {
            // burst-publish chunk 0 into buffer 0, prefetch chunk 1
            sts_chunk(pv, xw, lane);
            ldg_chunk(pv, x, base_w, lane, 1);

            // consume l=0 (s8=0 -> pos = row), init merged from core_first
            float4 xa = *(const float4*)(xw + lane * 4);
            float4 xb = *(const float4*)(xw + (32 + lane) * 4);
            float mA[8], mB[8];
            #pragma unroll
            for (int k = 0; k < 8; ++k) {
                mA[k] = sfirst[k] * xa.x + sfirst[8 + k] * xa.y
                      + sfirst[16 + k] * xa.z + sfirst[24 + k] * xa.w;
                mB[k] = sfirst[k] * xb.x + sfirst[8 + k] * xb.y
                      + sfirst[16 + k] * xb.z + sfirst[24 + k] * xb.w;
            }
            #pragma unroll
            for (int p = 0; p < 4; ++p) {
                mpA[p] = fpack(mA[2 * p], mA[2 * p + 1]);
                mpB[p] = fpack(mB[2 * p], mB[2 * p + 1]);
            }

            // t=0 drip of chunk 1 into buffer 1 (one-time LDG-wait, amortized)
            sts_it(pv, xw + 2048, lane, 0);
            sts_it(pv, xw + 2048, lane, 1);
        }

        const float* cp = score;
        #pragma unroll 2
        for (int sc = 0; sc < HALF; ++sc) {
            const int l = phase * HALF + sc + 1;       // x index consumed this step
            const int t = l & 7;
            const int c = l >> 3;

            // x reads from buffer c&1 (issue early to hide LDS latency)
            const float* xc = xw + (c & 1) * 2048;
            float4 xa = *(const float4*)(xc + (t * 64 + ((lane + t) & 63)) * 4);
            float4 xb = *(const float4*)(xc + (t * 64 + ((lane + 32 + t) & 63)) * 4);

            // drip: 2 STS.128 of chunk c+1 (pv) into the inactive buffer
            if (c < 15 && !(c == 0 && t == 0)) {       // t=0 of chunk 0 done in init
                float* nb = xw + ((c + 1) & 1) * 2048;
                sts_it(pv, nb, lane, 2 * t);
                sts_it(pv, nb, lane, 2 * t + 1);
            }
            // prefetch chunk c+2 AFTER the last drip-stores of chunk c+1
            // have read pv (t==7; register WAR order guarantees safety)
            if (t == 7 && c < 14) ldg_chunk(pv, x, base_w, lane, c + 2);

            // duplicate merged scalars into packed lanes
            u64 mdA[8], mdB[8];
            #pragma unroll
            for (int p = 0; p < 4; ++p) {
                float a0, a1, b0, b1;
                funpack(mpA[p], a0, a1);
                funpack(mpB[p], b0, b1);
                mdA[2 * p] = fdup(a0); mdA[2 * p + 1] = fdup(a1);
                mdB[2 * p] = fdup(b0); mdB[2 * p + 1] = fdup(b1);
            }

            u64 Ya[3][4], Yb[3][4];
            #pragma unroll
            for (int j = 0; j < 3; ++j) {
                const float* cj = cp + j * 64;
                #pragma unroll
                for (int k = 0; k < 8; ++k) {
                    ulonglong2 cA = *(const ulonglong2*)(cj + k * 8);
                    ulonglong2 cB = *(const ulonglong2*)(cj + k * 8 + 4);
                    if (k == 0) {
                        Ya[j][0] = f2mul(mdA[0], cA.x); Ya[j][1] = f2mul(mdA[0], cA.y);
                        Ya[j][2] = f2mul(mdA[0], cB.x); Ya[j][3] = f2mul(mdA[0], cB.y);
                        Yb[j][0] = f2mul(mdB[0], cA.x); Yb[j][1] = f2mul(mdB[0], cA.y);
                        Yb[j][2] = f2mul(mdB[0], cB.x); Yb[j][3] = f2mul(mdB[0], cB.y);
                    } else {
                        Ya[j][0] = f2fma(mdA[k], cA.x, Ya[j][0]);
                        Ya[j][1] = f2fma(mdA[k], cA.y, Ya[j][1]);
                        Ya[j][2] = f2fma(mdA[k], cB.x, Ya[j][2]);
                        Ya[j][3] = f2fma(mdA[k], cB.y, Ya[j][3]);
                        Yb[j][0] = f2fma(mdB[k], cA.x, Yb[j][0]);
                        Yb[j][1] = f2fma(mdB[k], cA.y, Yb[j][1]);
                        Yb[j][2] = f2fma(mdB[k], cB.x, Yb[j][2]);
                        Yb[j][3] = f2fma(mdB[k], cB.y, Yb[j][3]);
                    }
                }
            }

            // identity slice: j=3 term is x3 * merged (exact)
            const u64 a0 = fdup(xa.x), a1 = fdup(xa.y), a2 = fdup(xa.z), a3 = fdup(xa.w);
            const u64 b0 = fdup(xb.x), b1 = fdup(xb.y), b2 = fdup(xb.z), b3 = fdup(xb.w);
            #pragma unroll
            for (int p = 0; p < 4; ++p) {
                mpA[p] = f2fma(a3, mpA[p],
                         f2fma(a2, Ya[2][p],
                         f2fma(a1, Ya[1][p],
                         f2mul(a0, Ya[0][p]))));
                mpB[p] = f2fma(b3, mpB[p],
                         f2fma(b2, Yb[2][p],
                         f2fma(b1, Yb[1][p],
                         f2mul(b0, Yb[0][p]))));
            }
            cp += 3 * 64;
        }
    }

    // ---- final contraction with core_last: out[l] = sum_j x_j (sum_k m_k C[k][j][l]) ----
    {
        const int t = 127 & 7;                 // 7, chunk 15 -> buffer 1
        const float* xc = xw + 2048;
        float4 xa = *(const float4*)(xc + (t * 64 + ((lane + t) & 63)) * 4);
        float4 xb = *(const float4*)(xc + (t * 64 + ((lane + 32 + t) & 63)) * 4);

        u64 mdA[8], mdB[8];
        #pragma unroll
        for (int p = 0; p < 4; ++p) {
            float a0, a1, b0, b1;
            funpack(mpA[p], a0, a1);
            funpack(mpB[p], b0, b1);
            mdA[2 * p] = fdup(a0); mdA[2 * p + 1] = fdup(a1);
            mdB[2 * p] = fdup(b0); mdB[2 * p + 1] = fdup(b1);
        }
        u64 YlA[4], YlB[4];
        #pragma unroll
        for (int j = 0; j < 4; ++j) {
            u64 accA = f2mul(mdA[0], *(const u64*)(slast + j * 2));
            u64 accB = f2mul(mdB[0], *(const u64*)(slast + j * 2));
            #pragma unroll
            for (int k = 1; k < 8; ++k) {
                u64 cv = *(const u64*)(slast + (k * DV + j) * 2);
                accA = f2fma(mdA[k], cv, accA);
                accB = f2fma(mdB[k], cv, accB);
            }
            YlA[j] = accA; YlB[j] = accB;
        }
        u64 oA = f2fma(fdup(xa.w), YlA[3],
                 f2fma(fdup(xa.z), YlA[2],
                 f2fma(fdup(xa.y), YlA[1],
                 f2mul(fdup(xa.x), YlA[0]))));
        u64 oB = f2fma(fdup(xb.w), YlB[3],
                 f2fma(fdup(xb.z), YlB[2],
                 f2fma(fdup(xb.y), YlB[1],
                 f2mul(fdup(xb.x), YlB[0]))));
        float r0, r1;
        if (n0 < n_total) {
            funpack(oA, r0, r1);
            float2 res; res.x = r0; res.y = r1;
            *(float2*)(out + 2 * (size_t)n0) = res;
        }
        if (n1 < n_total) {
            funpack(oB, r0, r1);
            float2 res; res.x = r0; res.y = r1;
            *(float2*)(out + 2 * (size_t)n1) = res;
        }
    }
}

extern "C" void kernel_launch(void* const* d_in, const int* in_sizes, int n_in,
                              void* d_out, int out_size)
{
    const float* x  = (const float*)d_in[0];
    const float* cf = (const float*)d_in[1];
    const float* cm = (const float*)d_in[2];
    const float* cl = (const float*)d_in[3];
    float* out = (float*)d_out;

    const int n_total = in_sizes[0] / (LV * DV);   // 65536

    cudaFuncSetAttribute(tt_chain_kernel,
                         cudaFuncAttributeMaxDynamicSharedMemorySize, SMEM_BYTES);

    const int threads = 128;
    const int blocks = (n_total + 255) / 256;      // 2 samples per thread
    tt_chain_kernel<<<blocks, threads, SMEM_BYTES>>>(x, cf, cm, cl, out, n_total);
}

// round 11
// speedup vs baseline: 1.1502x; 1.1502x over previous
#include <cuda_runtime.h>

// SGD_Hankel TT-chain: N=65536, L=128, D=4, R=8, O=2.
// R11: pair-split restructure. Each sample's 4 output-pairs are split across
// lane i (pairs 0,1) and lane i+16 (pairs 2,3); merged halves are exchanged
// per step with shfl.xor(16). A warp covers 32 samples (2 per lane-half) =>
// total warps double => 4 warps/SMSP (was 2) at the same occupancy/grid
// shape, while per-warp FMA and core-LDS both halve. Core rows are read in
// (k+4h)&7 order so own rows land in md[0..3] with no lane-dependent selects
// and h=0 lanes end with true-order merged for the epilogue.
// x staging: R6/R7-proven burst pattern (register prefetch pv[8], burst
// STS/LDG at chunk boundaries, warp-private buffer, no syncs).

#define DV 4
#define RV 8
#define LV 128
#define HALF  63

typedef unsigned long long u64;

__device__ __forceinline__ u64 fpack(float a, float b) {
    u64 r; asm("mov.b64 %0, {%1,%2};" : "=l"(r) : "f"(a), "f"(b)); return r;
}
__device__ __forceinline__ u64 fdup(float a) {
    u64 r; asm("mov.b64 %0, {%1,%1};" : "=l"(r) : "f"(a)); return r;
}
__device__ __forceinline__ void funpack(u64 v, float& a, float& b) {
    asm("mov.b64 {%0,%1}, %2;" : "=f"(a), "=f"(b) : "l"(v));
}
__device__ __forceinline__ u64 f2mul(u64 a, u64 b) {
    u64 d; asm("mul.rn.f32x2 %0, %1, %2;" : "=l"(d) : "l"(a), "l"(b)); return d;
}
__device__ __forceinline__ u64 f2fma(u64 a, u64 b, u64 c) {
    u64 d; asm("fma.rn.f32x2 %0, %1, %2, %3;" : "=l"(d) : "l"(a), "l"(b), "l"(c)); return d;
}

// smem: cores [63][3][8][8] + xbuf 8 warps * 1024 floats + first/last
#define SCORE_FLOATS (HALF * 3 * RV * RV)      // 12096
#define XBUF_FLOATS  (8 * 1024)                // 8192 (4KB per warp)
#define SFL_OFF      (SCORE_FLOATS + XBUF_FLOATS)
#define SMEM_FLOATS  (SFL_OFF + 96)
#define SMEM_BYTES   (SMEM_FLOATS * 4)         // 81536

// 8 coalesced LDG.128 for chunk c (warp covers 32 consecutive samples).
__device__ __forceinline__ void ldg_chunk(float4 (&pv)[8], const float* __restrict__ x,
                                          int base_w, int lane, int c)
{
    const int s8 = lane & 7;
    const int g  = lane >> 3;
    #pragma unroll
    for (int it = 0; it < 8; ++it) {
        int n = base_w + g + it * 4;                  // sample
        pv[it] = *(const float4*)(x + (size_t)n * (LV * DV) + (c * 8 + s8) * 4);
    }
}

// Publish chunk: 8 STS.128, swizzle pos=(sample+s8)&31. Layout [s8][pos] float4.
__device__ __forceinline__ void sts_chunk(const float4 (&pv)[8], float* xw, int lane)
{
    const int s8 = lane & 7;
    const int g  = lane >> 3;
    #pragma unroll
    for (int it = 0; it < 8; ++it) {
        int smp = g + it * 4;
        int pos = (smp + s8) & 31;
        *(float4*)(xw + (s8 * 32 + pos) * 4) = pv[it];
    }
}

extern "C" __global__ void __launch_bounds__(256, 2)
tt_chain_kernel(const float* __restrict__ x,
                const float* __restrict__ core_first,
                const float* __restrict__ cores_mid,
                const float* __restrict__ core_last,
                float* __restrict__ out,
                int n_total)
{
    extern __shared__ float sm[];
    float* score  = sm;                    // [63][3][8][8]
    float* xbuf   = sm + SCORE_FLOATS;
    float* sfirst = sm + SFL_OFF;          // 32 floats [j][k]
    float* slast  = sfirst + 32;           // 64 floats [k][j][l]

    const int tid  = threadIdx.x;
    const int lane = tid & 31;
    const int w    = tid >> 5;
    const int jj   = lane & 15;            // sample sub-index within warp half
    const int h    = lane >> 4;            // pair-half: 0 -> pairs 0,1; 1 -> pairs 2,3
    float* xw = xbuf + w * 1024;

    const int base_w = blockIdx.x * 256 + w * 32;
    const int sA = base_w + jj;            // this lane-pair's samples
    const int sB = sA + 16;

    // lane constants for permuted core-row addressing:
    // own rows (k = 4h..4h+3) come first: offsets oA + {0,8,16,24};
    // partner rows next: offsets oB + {0,8,16,24}.
    const int oA = h ? 36 : 0;             // h=1: row4..7 at 32.. + pair-half 4
    const int oB = h ? 4  : 32;            // h=1: row0..3 + 4 ; h=0: row4..7

    float4 pv[8];
    ldg_chunk(pv, x, base_w, lane, 0);     // overlap with core staging

    if (tid < 32)       sfirst[tid] = core_first[tid];
    else if (tid < 96)  slast[tid - 32] = core_last[tid - 32];

    u64 mpA[2], mpB[2];                    // own 2 pairs (packed values)
    u64 mdA[8], mdB[8];                    // duplicated merged, permuted order

    #pragma unroll 1
    for (int phase = 0; phase < 2; ++phase) {
        __syncthreads();
        for (int u = tid; u < HALF * 48; u += 256) {
            int st = u / 48;
            int rr = u - st * 48;
            int j = rr >> 4, k = (rr >> 1) & 7, hh = rr & 1;
            float4 v = *(const float4*)(cores_mid
                        + (((size_t)(phase * HALF + st) * RV + k) * DV + j) * RV + hh * 4);
            *(float4*)(score + ((st * 3 + j) * RV + k) * RV + hh * 4) = v;
        }
        __syncthreads();

        if (phase == 0) {
            sts_chunk(pv, xw, lane);
            ldg_chunk(pv, x, base_w, lane, 1);

            // l=0 (s8=0 -> pos=sample): init merged from core_first
            float4 xa = *(const float4*)(xw + jj * 4);
            float4 xb = *(const float4*)(xw + (16 + jj) * 4);
            float mA[8], mB[8];
            #pragma unroll
            for (int k = 0; k < 8; ++k) {
                mA[k] = sfirst[k] * xa.x + sfirst[8 + k] * xa.y
                      + sfirst[16 + k] * xa.z + sfirst[24 + k] * xa.w;
                mB[k] = sfirst[k] * xb.x + sfirst[8 + k] * xb.y
                      + sfirst[16 + k] * xb.z + sfirst[24 + k] * xb.w;
            }
            // own pairs (h-select, init only)
            mpA[0] = h ? fpack(mA[4], mA[5]) : fpack(mA[0], mA[1]);
            mpA[1] = h ? fpack(mA[6], mA[7]) : fpack(mA[2], mA[3]);
            mpB[0] = h ? fpack(mB[4], mB[5]) : fpack(mB[0], mB[1]);
            mpB[1] = h ? fpack(mB[6], mB[7]) : fpack(mB[2], mB[3]);
            // md in permuted order: md[kk] = m[(kk+4h)&7]
            #pragma unroll
            for (int kk = 0; kk < 8; ++kk) {
                int lo = kk & 3;
                mdA[kk] = fdup((kk < 4) == (h == 0) ? mA[lo] : mA[lo + 4]);
                mdB[kk] = fdup((kk < 4) == (h == 0) ? mB[lo] : mB[lo + 4]);
            }
        }

        const float* cp = score;
        #pragma unroll 1
        for (int sc = 0; sc < HALF; ++sc) {
            const int l = phase * HALF + sc + 1;
            if ((l & 7) == 0) {
                sts_chunk(pv, xw, lane);               // warp-private: no sync needed
                const int c = l >> 3;
                if (c < 15) ldg_chunk(pv, x, base_w, lane, c + 1);
            }
            const int t = l & 7;

            float4 xa = *(const float4*)(xw + (t * 32 + ((jj + t) & 31)) * 4);
            float4 xb = *(const float4*)(xw + (t * 32 + ((jj + 16 + t) & 31)) * 4);

            // Y build: own 2 pairs only; rows in permuted order matching md
            u64 Ya[3][2], Yb[3][2];
            #pragma unroll
            for (int j = 0; j < 3; ++j) {
                const float* c1 = cp + j * 64 + oA;    // own rows (md[0..3])
                const float* c2 = cp + j * 64 + oB;    // partner rows (md[4..7])
                #pragma unroll
                for (int kk = 0; kk < 4; ++kk) {
                    ulonglong2 cv = *(const ulonglong2*)(c1 + kk * 8);
                    if (kk == 0) {
                        Ya[j][0] = f2mul(mdA[0], cv.x); Ya[j][1] = f2mul(mdA[0], cv.y);
                        Yb[j][0] = f2mul(mdB[0], cv.x); Yb[j][1] = f2mul(mdB[0], cv.y);
                    } else {
                        Ya[j][0] = f2fma(mdA[kk], cv.x, Ya[j][0]);
                        Ya[j][1] = f2fma(mdA[kk], cv.y, Ya[j][1]);
                        Yb[j][0] = f2fma(mdB[kk], cv.x, Yb[j][0]);
                        Yb[j][1] = f2fma(mdB[kk], cv.y, Yb[j][1]);
                    }
                }
                #pragma unroll
                for (int kk = 0; kk < 4; ++kk) {
                    ulonglong2 cv = *(const ulonglong2*)(c2 + kk * 8);
                    Ya[j][0] = f2fma(mdA[4 + kk], cv.x, Ya[j][0]);
                    Ya[j][1] = f2fma(mdA[4 + kk], cv.y, Ya[j][1]);
                    Yb[j][0] = f2fma(mdB[4 + kk], cv.x, Yb[j][0]);
                    Yb[j][1] = f2fma(mdB[4 + kk], cv.y, Yb[j][1]);
                }
            }

            // combine (identity slice: j=3 term = x3 * own merged pairs)
            const u64 a0 = fdup(xa.x), a1 = fdup(xa.y), a2 = fdup(xa.z), a3 = fdup(xa.w);
            const u64 b0 = fdup(xb.x), b1 = fdup(xb.y), b2 = fdup(xb.z), b3 = fdup(xb.w);
            #pragma unroll
            for (int p = 0; p < 2; ++p) {
                mpA[p] = f2fma(a3, mpA[p],
                         f2fma(a2, Ya[2][p],
                         f2fma(a1, Ya[1][p],
                         f2mul(a0, Ya[0][p]))));
                mpB[p] = f2fma(b3, mpB[p],
                         f2fma(b2, Yb[2][p],
                         f2fma(b1, Yb[1][p],
                         f2mul(b0, Yb[0][p]))));
            }

            // exchange halves + rebuild duplicated merged (own -> md[0..3])
            u64 qA0 = __shfl_xor_sync(0xFFFFFFFFu, mpA[0], 16);
            u64 qA1 = __shfl_xor_sync(0xFFFFFFFFu, mpA[1], 16);
            u64 qB0 = __shfl_xor_sync(0xFFFFFFFFu, mpB[0], 16);
            u64 qB1 = __shfl_xor_sync(0xFFFFFFFFu, mpB[1], 16);
            {
                float u0, v0;
                funpack(mpA[0], u0, v0); mdA[0] = fdup(u0); mdA[1] = fdup(v0);
                funpack(mpA[1], u0, v0); mdA[2] = fdup(u0); mdA[3] = fdup(v0);
                funpack(qA0,    u0, v0); mdA[4] = fdup(u0); mdA[5] = fdup(v0);
                funpack(qA1,    u0, v0); mdA[6] = fdup(u0); mdA[7] = fdup(v0);
                funpack(mpB[0], u0, v0); mdB[0] = fdup(u0); mdB[1] = fdup(v0);
                funpack(mpB[1], u0, v0); mdB[2] = fdup(u0); mdB[3] = fdup(v0);
                funpack(qB0,    u0, v0); mdB[4] = fdup(u0); mdB[5] = fdup(v0);
                funpack(qB1,    u0, v0); mdB[6] = fdup(u0); mdB[7] = fdup(v0);
            }
            cp += 3 * 64;
        }
    }

    // ---- final contraction (h=0 lanes hold TRUE-order md after the loop's
    //      exchange: md[0..3]=pairs0,1  md[4..7]=pairs2,3) ----
    if (h == 0) {
        const int t = 7;                       // l=127, chunk 15 staged
        float4 xa = *(const float4*)(xw + (t * 32 + ((jj + t) & 31)) * 4);
        float4 xb = *(const float4*)(xw + (t * 32 + ((jj + 16 + t) & 31)) * 4);

        u64 YlA[4], YlB[4];
        #pragma unroll
        for (int j = 0; j < 4; ++j) {
            u64 accA = f2mul(mdA[0], *(const u64*)(slast + j * 2));
            u64 accB = f2mul(mdB[0], *(const u64*)(slast + j * 2));
            #pragma unroll
            for (int k = 1; k < 8; ++k) {
                u64 cv = *(const u64*)(slast + (k * DV + j) * 2);
                accA = f2fma(mdA[k], cv, accA);
                accB = f2fma(mdB[k], cv, accB);
            }
            YlA[j] = accA; YlB[j] = accB;
        }
        u64 oAv = f2fma(fdup(xa.w), YlA[3],
                  f2fma(fdup(xa.z), YlA[2],
                  f2fma(fdup(xa.y), YlA[1],
                  f2mul(fdup(xa.x), YlA[0]))));
        u64 oBv = f2fma(fdup(xb.w), YlB[3],
                  f2fma(fdup(xb.z), YlB[2],
                  f2fma(fdup(xb.y), YlB[1],
                  f2mul(fdup(xb.x), YlB[0]))));
        float r0, r1;
        funpack(oAv, r0, r1);
        { float2 res; res.x = r0; res.y = r1; *(float2*)(out + 2 * (size_t)sA) = res; }
        funpack(oBv, r0, r1);
        { float2 res; res.x = r0; res.y = r1; *(float2*)(out + 2 * (size_t)sB) = res; }
    }
}

extern "C" void kernel_launch(void* const* d_in, const int* in_sizes, int n_in,
                              void* d_out, int out_size)
{
    const float* x  = (const float*)d_in[0];
    const float* cf = (const float*)d_in[1];
    const float* cm = (const float*)d_in[2];
    const float* cl = (const float*)d_in[3];
    float* out = (float*)d_out;

    const int n_total = in_sizes[0] / (LV * DV);   // 65536

    cudaFuncSetAttribute(tt_chain_kernel,
                         cudaFuncAttributeMaxDynamicSharedMemorySize, SMEM_BYTES);

    const int threads = 256;                       // 8 warps, 32 samples/warp
    const int blocks = (n_total + 255) / 256;      // 256 CTAs
    tt_chain_kernel<<<blocks, threads, SMEM_BYTES>>>(x, cf, cm, cl, out, n_total);
}